// round 1
// baseline (speedup 1.0000x reference)
#include <cuda_runtime.h>
#include <cstdint>

// HELoss: loss = mean_i [ logsumexp_j(s*logits[i,j] with label col -> s*(l_y - cm)) - s*(l_y - cm) ]
// N=8192 rows, C=32000 cols, s=30. Pure HBM-bound streaming row-LSE.

constexpr int N_ROWS = 8192;
constexpr int N_COLS = 32000;
constexpr int NVEC   = N_COLS / 4;      // 8000 float4 per row
constexpr float S_SCALE = 30.0f;
constexpr float K_L2E   = 30.0f * 1.44269504088896340736f; // S * log2(e)
constexpr float LN2F    = 0.693147180559945309f;
constexpr float NEG_BIG = -3.402823466e38f;

__device__ float g_row_loss[N_ROWS];
__device__ int   g_is64;

static __device__ __forceinline__ float ex2f_(float x) {
    float y; asm("ex2.approx.ftz.f32 %0, %1;" : "=f"(y) : "f"(x)); return y;
}
static __device__ __forceinline__ float lg2f_(float x) {
    float y; asm("lg2.approx.ftz.f32 %0, %1;" : "=f"(y) : "f"(x)); return y;
}

// Detect whether the labels buffer is int64 (little-endian: odd 32-bit words all
// zero, since 0 <= label < 32000) or int32. 1024 odd words all zero by chance
// for int32 random labels has probability ~(1/32000)^1024 ~= 0.
__global__ void detect_label_width(const unsigned int* __restrict__ raw) {
    bool allz = true;
    for (int i = threadIdx.x; i < 1024; i += 32)
        allz &= (raw[2 * i + 1] == 0u);
    unsigned int mask = __ballot_sync(0xffffffffu, allz);
    if (threadIdx.x == 0) g_is64 = (mask == 0xffffffffu) ? 1 : 0;
}

__global__ void __launch_bounds__(256)
row_lse_kernel(const float* __restrict__ logits,
               const void*  __restrict__ labels,
               const float* __restrict__ cm_ptr) {
    const int row = blockIdx.x;
    const int tid = threadIdx.x;

    int lab;
    if (g_is64) lab = (int)((const long long*)labels)[row];
    else        lab = ((const int*)labels)[row];

    const float cm = __ldg(cm_ptr);
    const float* rowp = logits + (size_t)row * N_COLS;
    const float4* vp  = (const float4*)rowp;
    const int lvec  = lab >> 2;
    const int llane = lab & 3;

    float m   = NEG_BIG;   // running max of effective raw logits
    float s   = 0.0f;      // sum of exp2(K*(x - m))
    float nmK = 0.0f;      // -m * K

    // 8 iterations x 4 float4 x 256 threads = 8192 vecs (>= 8000, tail masked)
    #pragma unroll
    for (int it = 0; it < 8; ++it) {
        float4 v[4];
        int idx0 = tid + (it * 4) * 256;
        #pragma unroll
        for (int j = 0; j < 4; ++j) {
            int idx = idx0 + j * 256;
            if (idx < NVEC) v[j] = vp[idx];
            else            v[j] = make_float4(NEG_BIG, NEG_BIG, NEG_BIG, NEG_BIG);
        }
        // Label-column substitution: x_label -> x_label - cm (rare branch)
        #pragma unroll
        for (int j = 0; j < 4; ++j) {
            int idx = idx0 + j * 256;
            if (idx == lvec) {
                if (llane == 0) v[j].x -= cm;
                else if (llane == 1) v[j].y -= cm;
                else if (llane == 2) v[j].z -= cm;
                else v[j].w -= cm;
            }
        }
        // chunk max over 16 values (tree)
        float a0 = fmaxf(fmaxf(v[0].x, v[0].y), fmaxf(v[0].z, v[0].w));
        float a1 = fmaxf(fmaxf(v[1].x, v[1].y), fmaxf(v[1].z, v[1].w));
        float a2 = fmaxf(fmaxf(v[2].x, v[2].y), fmaxf(v[2].z, v[2].w));
        float a3 = fmaxf(fmaxf(v[3].x, v[3].y), fmaxf(v[3].z, v[3].w));
        float cmx = fmaxf(fmaxf(a0, a1), fmaxf(a2, a3));
        float nm = fmaxf(m, cmx);
        float scale = ex2f_((m - nm) * K_L2E);  // ==1 when max unchanged; 0 on first chunk
        m = nm;
        nmK = -m * K_L2E;
        // sum of 16 exps (pairwise tree for ILP)
        float e00 = ex2f_(fmaf(v[0].x, K_L2E, nmK));
        float e01 = ex2f_(fmaf(v[0].y, K_L2E, nmK));
        float e02 = ex2f_(fmaf(v[0].z, K_L2E, nmK));
        float e03 = ex2f_(fmaf(v[0].w, K_L2E, nmK));
        float e10 = ex2f_(fmaf(v[1].x, K_L2E, nmK));
        float e11 = ex2f_(fmaf(v[1].y, K_L2E, nmK));
        float e12 = ex2f_(fmaf(v[1].z, K_L2E, nmK));
        float e13 = ex2f_(fmaf(v[1].w, K_L2E, nmK));
        float e20 = ex2f_(fmaf(v[2].x, K_L2E, nmK));
        float e21 = ex2f_(fmaf(v[2].y, K_L2E, nmK));
        float e22 = ex2f_(fmaf(v[2].z, K_L2E, nmK));
        float e23 = ex2f_(fmaf(v[2].w, K_L2E, nmK));
        float e30 = ex2f_(fmaf(v[3].x, K_L2E, nmK));
        float e31 = ex2f_(fmaf(v[3].y, K_L2E, nmK));
        float e32 = ex2f_(fmaf(v[3].z, K_L2E, nmK));
        float e33 = ex2f_(fmaf(v[3].w, K_L2E, nmK));
        float t0 = (e00 + e01) + (e02 + e03);
        float t1 = (e10 + e11) + (e12 + e13);
        float t2 = (e20 + e21) + (e22 + e23);
        float t3 = (e30 + e31) + (e32 + e33);
        float csum = (t0 + t1) + (t2 + t3);
        s = fmaf(s, scale, csum);
    }

    // warp combine (m, s)
    #pragma unroll
    for (int o = 16; o > 0; o >>= 1) {
        float mo = __shfl_down_sync(0xffffffffu, m, o);
        float so = __shfl_down_sync(0xffffffffu, s, o);
        float M  = fmaxf(m, mo);
        s = s * ex2f_((m - M) * K_L2E) + so * ex2f_((mo - M) * K_L2E);
        m = M;
    }

    __shared__ float sm_m[8];
    __shared__ float sm_s[8];
    int wid = tid >> 5;
    if ((tid & 31) == 0) { sm_m[wid] = m; sm_s[wid] = s; }
    __syncthreads();

    if (tid < 32) {
        float m2 = (tid < 8) ? sm_m[tid] : NEG_BIG;
        float s2 = (tid < 8) ? sm_s[tid] : 0.0f;
        #pragma unroll
        for (int o = 4; o > 0; o >>= 1) {
            float mo = __shfl_down_sync(0xffffffffu, m2, o);
            float so = __shfl_down_sync(0xffffffffu, s2, o);
            float M  = fmaxf(m2, mo);
            s2 = s2 * ex2f_((m2 - M) * K_L2E) + so * ex2f_((mo - M) * K_L2E);
            m2 = M;
        }
        if (tid == 0) {
            float ly  = __ldg(rowp + lab);
            float num = S_SCALE * (ly - cm);
            // lse_natural = S*m + ln(s)
            float lse = S_SCALE * m2 + lg2f_(s2) * LN2F;
            g_row_loss[row] = lse - num;  // per-row contribution to mean(lse - num)
        }
    }
}

__global__ void __launch_bounds__(1024)
final_reduce_kernel(float* __restrict__ out) {
    const int tid = threadIdx.x;
    float a = 0.0f;
    #pragma unroll
    for (int i = 0; i < N_ROWS / 1024; ++i)
        a += g_row_loss[tid + i * 1024];
    #pragma unroll
    for (int o = 16; o > 0; o >>= 1)
        a += __shfl_down_sync(0xffffffffu, a, o);
    __shared__ float sm[32];
    if ((tid & 31) == 0) sm[tid >> 5] = a;
    __syncthreads();
    if (tid < 32) {
        float b = sm[tid];   // exactly 32 warps
        #pragma unroll
        for (int o = 16; o > 0; o >>= 1)
            b += __shfl_down_sync(0xffffffffu, b, o);
        if (tid == 0) out[0] = b * (1.0f / (float)N_ROWS);
    }
}

extern "C" void kernel_launch(void* const* d_in, const int* in_sizes, int n_in,
                              void* d_out, int out_size) {
    const float* logits = (const float*)d_in[0];
    const void*  labels = d_in[1];
    const float* cm     = (const float*)d_in[2];
    float* out = (float*)d_out;

    detect_label_width<<<1, 32>>>((const unsigned int*)labels);
    row_lse_kernel<<<N_ROWS, 256>>>(logits, labels, cm);
    final_reduce_kernel<<<1, 1024>>>(out);
}